// round 11
// baseline (speedup 1.0000x reference)
#include <cuda_runtime.h>
#include <cmath>

#define BB 4
#define NN 2048
#define FF 128
#define HH 4
#define DD 32
#define MSPLIT 9
#define CROWS 128
#define MT 64

// ---- k_attn smem layout (byte offsets inside one buffer) ----
#define OFFH 0                     // 64 rows * 128 f32 (swizzled)   = 32768 B
#define OFFE 32768                 // 64 nodes * 4 heads * float4    =  4096 B
#define OFFA 36864                 // 128 rows * 68 chars            =  8704 B
#define BUFB 45568                 // one buffer
#define ATTN_SMEM (2 * BUFB)       // 91136 B, double buffered

// ---------------- scratch (no allocations allowed) ----------------
__device__ float         g_h[BB * NN * FF];
__device__ float4        g_src[BB * NN * HH];   // (e_src, exp(e_src), exp(0.2 e_src), 0)
__device__ float4        g_dst[BB * NN * HH];
__device__ unsigned char g_adj8[NN * NN];
__device__ float         g_num[MSPLIT * BB * NN * FF];
__device__ float         g_den[MSPLIT * BB * NN * HH];

// ---------------- helpers ----------------
__device__ __forceinline__ unsigned long long ffma2(unsigned long long a,
                                                    unsigned long long b,
                                                    unsigned long long c) {
    unsigned long long d;
    asm("fma.rn.f32x2 %0, %1, %2, %3;" : "=l"(d) : "l"(a), "l"(b), "l"(c));
    return d;
}
__device__ __forceinline__ unsigned long long pack2(float x) {
    unsigned long long d;
    asm("mov.b64 %0, {%1, %1};" : "=l"(d) : "f"(x));
    return d;
}
__device__ __forceinline__ unsigned int smem_u32(const void* p) {
    unsigned int a;
    asm("{ .reg .u64 t; cvta.to.shared.u64 t, %1; cvt.u32.u64 %0, t; }"
        : "=r"(a) : "l"(p));
    return a;
}
__device__ __forceinline__ void cp16(unsigned int dst, const void* src) {
    asm volatile("cp.async.cg.shared.global [%0], [%1], 16;" :: "r"(dst), "l"(src));
}
__device__ __forceinline__ void cp_commit() {
    asm volatile("cp.async.commit_group;");
}
__device__ __forceinline__ void cp_wait0() {
    asm volatile("cp.async.wait_group 0;");
}

// ---------------- Kernel A: h = x @ W^T ----------------
#define A_SMEM ((128 * 132 + 64 * 132) * 4)

__global__ void __launch_bounds__(256) k_gemm(const float* __restrict__ x,
                                              const float* __restrict__ W) {
    extern __shared__ float sm[];
    float* shW = sm;
    float* shX = sm + 128 * 132;
    const int tid = threadIdx.x;
    const int row0 = blockIdx.x * 64;

    #pragma unroll
    for (int t = 0; t < 16; t++) {
        int idx = tid + t * 256;
        int o = idx >> 5, i4 = idx & 31;
        float4 v = ((const float4*)W)[o * 32 + i4];
        *((float4*)(shW + o * 132 + 4 * i4)) = v;
    }
    #pragma unroll
    for (int t = 0; t < 8; t++) {
        int idx = tid + t * 256;
        int r = idx >> 5, i4 = idx & 31;
        float4 v = ((const float4*)x)[(size_t)(row0 + r) * 32 + i4];
        *((float4*)(shX + r * 132 + 4 * i4)) = v;
    }
    __syncthreads();

    const int r = tid >> 2, c = tid & 3;
    float acc[32];
    #pragma unroll
    for (int k = 0; k < 32; k++) acc[k] = 0.f;

    #pragma unroll 4
    for (int i4 = 0; i4 < 32; i4++) {
        float4 xv = *((const float4*)(shX + r * 132 + 4 * i4));
        #pragma unroll
        for (int k = 0; k < 32; k++) {
            int o = 4 * k + c;
            float4 wv = *((const float4*)(shW + o * 132 + 4 * i4));
            acc[k] = fmaf(xv.x, wv.x, acc[k]);
            acc[k] = fmaf(xv.y, wv.y, acc[k]);
            acc[k] = fmaf(xv.z, wv.z, acc[k]);
            acc[k] = fmaf(xv.w, wv.w, acc[k]);
        }
    }
    float* hrow = g_h + (size_t)(row0 + r) * FF;
    #pragma unroll
    for (int k = 0; k < 32; k++) hrow[4 * k + c] = acc[k];
}

// ---------------- Kernel B: edge terms + factored exps ----------------
__global__ void __launch_bounds__(256) k_edge(const float* __restrict__ a_src,
                                              const float* __restrict__ a_dst) {
    int idx = blockIdx.x * 256 + threadIdx.x;
    if (idx >= BB * NN * HH) return;
    int h = idx & 3;
    int bn = idx >> 2;
    const float* hp = g_h + (size_t)bn * FF + h * DD;
    const float* as = a_src + h * DD;
    const float* ad = a_dst + h * DD;
    float es = 0.f, ed = 0.f;
    #pragma unroll
    for (int d = 0; d < DD; d++) {
        float v = hp[d];
        es = fmaf(v, as[d], es);
        ed = fmaf(v, ad[d], ed);
    }
    g_src[idx] = make_float4(es, expf(es), expf(0.2f * es), 0.f);
    g_dst[idx] = make_float4(ed, expf(ed), expf(0.2f * ed), 0.f);
}

// ---------------- Kernel B2: adj int32 -> u8 ----------------
__global__ void __launch_bounds__(256) k_adj8(const int* __restrict__ adj) {
    int idx = blockIdx.x * 256 + threadIdx.x;         // 16 ints per thread
    const int4* p = (const int4*)adj + (size_t)idx * 4;
    int4 a0 = p[0], a1 = p[1], a2 = p[2], a3 = p[3];
    uint4 o;
    o.x = (unsigned)(a0.x | (a0.y << 8) | (a0.z << 16) | (a0.w << 24));
    o.y = (unsigned)(a1.x | (a1.y << 8) | (a1.z << 16) | (a1.w << 24));
    o.z = (unsigned)(a2.x | (a2.y << 8) | (a2.z << 16) | (a2.w << 24));
    o.w = (unsigned)(a3.x | (a3.y << 8) | (a3.z << 16) | (a3.w << 24));
    ((uint4*)g_adj8)[idx] = o;
}

// ---------------- Kernel C: fused masked-softmax aggregation (FFMA2) ----------------
// 256 threads: c = tid&3 (head), rg = tid>>2 (0..63), rows = n0+2rg, n0+2rg+1.
// Each thread owns 2 rows x one full head (32 cols = 16 packed-f32x2 accs/row).
// h tile swizzled: chunk q at q ^ ((q>>3)&7); reader of logical chunk 8c+s
// fetches slot 8c+(s^c) -> conflict-free LDS.128 with 8-way broadcast.
// e_dst tile: 64 nodes x 4 heads of float4 (4096 B), loaded by all 256 threads.
// adj tile u8, 68-B row stride. Double-buffered cp.async.
__global__ void __launch_bounds__(256, 2) k_attn() {
    extern __shared__ char smc[];
    const unsigned smaddr = smem_u32(smc);

    const int tid = threadIdx.x;
    const int c   = tid & 3;
    const int rg  = tid >> 2;
    const int b   = blockIdx.y;
    const int z   = blockIdx.z;
    const int n0  = blockIdx.x * CROWS;
    const int ra  = n0 + 2 * rg;

    const int tile0 = (z < 5) ? 4 * z : 3 * z + 5;
    const int nt    = (z < 5) ? 4 : 3;

    const float4 spa = g_src[(size_t)(b * NN + ra) * HH + c];
    const float4 spb = g_src[(size_t)(b * NN + ra + 1) * HH + c];

    unsigned long long accA[16], accB[16];
    #pragma unroll
    for (int k = 0; k < 16; k++) { accA[k] = 0ull; accB[k] = 0ull; }
    float dena = 0.f, denb = 0.f;

    const char* hsrc = (const char*)(g_h + (size_t)b * NN * FF);
    const char* esrc = (const char*)(g_dst + (size_t)b * NN * HH);

    // adj staging assignment: row = tid>>1, 32-char half = (tid&1)*32
    const int arow = tid >> 1;
    const int acol = (tid & 1) * 32;

    // ---- prologue: stage adj tile 0, issue cp.async tile 0 ----
    int m0 = tile0 * MT;
    uint4 st0 = *(const uint4*)(g_adj8 + (size_t)(n0 + arow) * NN + m0 + acol);
    uint4 st1 = *(const uint4*)(g_adj8 + (size_t)(n0 + arow) * NN + m0 + acol + 16);
    {
        unsigned bufa = smaddr;  // buffer 0
        #pragma unroll
        for (int t2 = 0; t2 < 8; t2++) {
            int gidx = tid + t2 * 256;
            int j = gidx >> 5, q = gidx & 31;
            int qs = q ^ ((q >> 3) & 7);
            cp16(bufa + OFFH + (j * 32 + qs) * 16,
                 hsrc + ((size_t)(m0 + j) * 128 + q * 4) * 4);
        }
        cp16(bufa + OFFE + tid * 16, esrc + ((size_t)m0 * HH + tid) * 16);
        cp_commit();
    }

    for (int t = 0; t < nt; t++) {
        const char* buf = smc + (t & 1) * BUFB;
        cp_wait0();
        // store staged adj for tile t into this buffer
        {
            unsigned* ad = (unsigned*)(buf + OFFA + arow * 68 + acol);
            ad[0] = st0.x; ad[1] = st0.y; ad[2] = st0.z; ad[3] = st0.w;
            ad[4] = st1.x; ad[5] = st1.y; ad[6] = st1.z; ad[7] = st1.w;
        }
        __syncthreads();   // adj + cp.async data visible to all warps

        if (t + 1 < nt) {  // prefetch tile t+1 into the other buffer
            int m1 = (tile0 + t + 1) * MT;
            st0 = *(const uint4*)(g_adj8 + (size_t)(n0 + arow) * NN + m1 + acol);
            st1 = *(const uint4*)(g_adj8 + (size_t)(n0 + arow) * NN + m1 + acol + 16);
            unsigned bufn = smaddr + ((t + 1) & 1) * BUFB;
            #pragma unroll
            for (int t2 = 0; t2 < 8; t2++) {
                int gidx = tid + t2 * 256;
                int j = gidx >> 5, q = gidx & 31;
                int qs = q ^ ((q >> 3) & 7);
                cp16(bufn + OFFH + (j * 32 + qs) * 16,
                     hsrc + ((size_t)(m1 + j) * 128 + q * 4) * 4);
            }
            cp16(bufn + OFFE + tid * 16, esrc + ((size_t)m1 * HH + tid) * 16);
            cp_commit();
        }

        const char* sh_h = buf + OFFH;
        const float4* sh_e = (const float4*)(buf + OFFE);
        const unsigned char* sh_adj = (const unsigned char*)(buf + OFFA);

        #pragma unroll 2
        for (int j = 0; j < MT; j++) {
            float4 ep = sh_e[j * HH + c];
            unsigned char aja = sh_adj[(2 * rg) * 68 + j];
            unsigned char ajb = sh_adj[(2 * rg + 1) * 68 + j];
            float za = spa.x + ep.x;
            float zb = spb.x + ep.x;
            float wa = (za > 0.f) ? spa.y * ep.y : spa.z * ep.z;
            float wb = (zb > 0.f) ? spb.y * ep.y : spb.z * ep.z;
            wa = aja ? wa : 0.f;
            wb = ajb ? wb : 0.f;
            dena += wa;
            denb += wb;
            unsigned long long wa2 = pack2(wa);
            unsigned long long wb2 = pack2(wb);
            const char* hrow = sh_h + j * 512;
            #pragma unroll
            for (int s = 0; s < 8; s++) {
                int qs = 8 * c + (s ^ c);
                ulonglong2 hv = *(const ulonglong2*)(hrow + qs * 16);
                accA[2 * s]     = ffma2(wa2, hv.x, accA[2 * s]);
                accA[2 * s + 1] = ffma2(wa2, hv.y, accA[2 * s + 1]);
                accB[2 * s]     = ffma2(wb2, hv.x, accB[2 * s]);
                accB[2 * s + 1] = ffma2(wb2, hv.y, accB[2 * s + 1]);
            }
        }
        __syncthreads();   // all warps done with buf before it is refilled
    }

    // ---- epilogue: partial numerators + denominators ----
    size_t obase = (size_t)z * (BB * NN * FF);
    ulonglong2* pa = (ulonglong2*)(g_num + obase + (size_t)(b * NN + ra) * FF + 32 * c);
    ulonglong2* pb = (ulonglong2*)(g_num + obase + (size_t)(b * NN + ra + 1) * FF + 32 * c);
    #pragma unroll
    for (int s = 0; s < 8; s++) {
        pa[s] = make_ulonglong2(accA[2 * s], accA[2 * s + 1]);
        pb[s] = make_ulonglong2(accB[2 * s], accB[2 * s + 1]);
    }
    size_t dbase = (size_t)z * (BB * NN * HH);
    g_den[dbase + (size_t)(b * NN + ra) * HH + c]     = dena;
    g_den[dbase + (size_t)(b * NN + ra + 1) * HH + c] = denb;
}

// ---------------- Kernel D: combine partials, normalize ----------------
__global__ void __launch_bounds__(256) k_combine(float* __restrict__ out) {
    int i4 = blockIdx.x * 256 + threadIdx.x;   // float4 index over B*N*F/4
    int bn = i4 >> 5;
    int head = (i4 >> 3) & 3;
    float sx = 0.f, sy = 0.f, sz = 0.f, sw = 0.f, den = 0.f;
    #pragma unroll
    for (int zz = 0; zz < MSPLIT; zz++) {
        float4 v = ((const float4*)(g_num + (size_t)zz * BB * NN * FF))[i4];
        sx += v.x; sy += v.y; sz += v.z; sw += v.w;
        den += g_den[(size_t)zz * BB * NN * HH + (size_t)bn * HH + head];
    }
    float inv = 1.f / den;
    ((float4*)out)[i4] = make_float4(sx * inv, sy * inv, sz * inv, sw * inv);
}

// ---------------- launch ----------------
extern "C" void kernel_launch(void* const* d_in, const int* in_sizes, int n_in,
                              void* d_out, int out_size) {
    const float* x     = (const float*)d_in[0];
    const int*   adj   = (const int*)d_in[1];
    const float* W     = (const float*)d_in[2];
    const float* a_src = (const float*)d_in[3];
    const float* a_dst = (const float*)d_in[4];
    float* out = (float*)d_out;

    cudaFuncSetAttribute(k_gemm, cudaFuncAttributeMaxDynamicSharedMemorySize, A_SMEM);
    cudaFuncSetAttribute(k_attn, cudaFuncAttributeMaxDynamicSharedMemorySize, ATTN_SMEM);

    k_adj8<<<NN * NN / 16 / 256, 256>>>(adj);
    k_gemm<<<(BB * NN) / 64, 256, A_SMEM>>>(x, W);
    k_edge<<<(BB * NN * HH) / 256, 256>>>(a_src, a_dst);
    dim3 gC(NN / CROWS, BB, MSPLIT);
    k_attn<<<gC, 256, ATTN_SMEM>>>();
    k_combine<<<(BB * NN * FF / 4) / 256, 256>>>(out);
}

// round 12
// speedup vs baseline: 1.2664x; 1.2664x over previous
#include <cuda_runtime.h>
#include <cmath>

#define BB 4
#define NN 2048
#define FF 128
#define HH 4
#define DD 32
#define MSPLIT 9
#define CROWS 128
#define MT 64

// ---- k_attn smem layout (byte offsets inside one buffer) ----
#define OFFH 0                     // 64 rows * 128 f32 (swizzled) = 32768 B
#define OFFE 32768                 // 64 j * 4 heads * float2      =  2048 B
#define OFFA 34816                 // 128 rows * u64 bitmask       =  1024 B
#define BUFB 35840
#define ATTN_SMEM (2 * BUFB)       // 71680 B double buffered

// ---------------- scratch ----------------
__device__ float              g_h[BB * NN * FF];
__device__ float2             g_srcp[BB * NN * HH];   // (exp(e_src), exp(0.2 e_src))
__device__ float2             g_dstp[BB * NN * HH];   // (exp(e_dst), exp(0.2 e_dst))
__device__ unsigned long long g_adjbit[NN * 32];      // bit j of [row][mtile]
__device__ float              g_num[MSPLIT * BB * NN * FF];
__device__ float              g_den[MSPLIT * BB * NN * HH];

// ---------------- helpers ----------------
__device__ __forceinline__ unsigned long long ffma2(unsigned long long a,
                                                    unsigned long long b,
                                                    unsigned long long c) {
    unsigned long long d;
    asm("fma.rn.f32x2 %0, %1, %2, %3;" : "=l"(d) : "l"(a), "l"(b), "l"(c));
    return d;
}
__device__ __forceinline__ unsigned long long mul2(unsigned long long a,
                                                   unsigned long long b) {
    unsigned long long d;
    asm("mul.rn.f32x2 %0, %1, %2;" : "=l"(d) : "l"(a), "l"(b));
    return d;
}
__device__ __forceinline__ unsigned long long pack2(float x) {
    unsigned long long d;
    asm("mov.b64 %0, {%1, %1};" : "=l"(d) : "f"(x));
    return d;
}
__device__ __forceinline__ unsigned long long pack2f(float lo, float hi) {
    unsigned long long d;
    asm("mov.b64 %0, {%1, %2};" : "=l"(d) : "f"(lo), "f"(hi));
    return d;
}
#define UNPACK2(lo, hi, v) \
    asm("mov.b64 {%0, %1}, %2;" : "=f"(lo), "=f"(hi) : "l"(v))
__device__ __forceinline__ unsigned int smem_u32(const void* p) {
    unsigned int a;
    asm("{ .reg .u64 t; cvta.to.shared.u64 t, %1; cvt.u32.u64 %0, t; }"
        : "=r"(a) : "l"(p));
    return a;
}
__device__ __forceinline__ void cp16(unsigned int dst, const void* src) {
    asm volatile("cp.async.cg.shared.global [%0], [%1], 16;" :: "r"(dst), "l"(src));
}
__device__ __forceinline__ void cp8(unsigned int dst, const void* src) {
    asm volatile("cp.async.ca.shared.global [%0], [%1], 8;" :: "r"(dst), "l"(src));
}
__device__ __forceinline__ void cp_commit() {
    asm volatile("cp.async.commit_group;");
}
__device__ __forceinline__ void cp_wait0() {
    asm volatile("cp.async.wait_group 0;");
}

// ---------------- Kernel A: h = x @ W^T ----------------
#define A_SMEM ((128 * 132 + 64 * 132) * 4)

__global__ void __launch_bounds__(256) k_gemm(const float* __restrict__ x,
                                              const float* __restrict__ W) {
    extern __shared__ float sm[];
    float* shW = sm;
    float* shX = sm + 128 * 132;
    const int tid = threadIdx.x;
    const int row0 = blockIdx.x * 64;

    #pragma unroll
    for (int t = 0; t < 16; t++) {
        int idx = tid + t * 256;
        int o = idx >> 5, i4 = idx & 31;
        float4 v = ((const float4*)W)[o * 32 + i4];
        *((float4*)(shW + o * 132 + 4 * i4)) = v;
    }
    #pragma unroll
    for (int t = 0; t < 8; t++) {
        int idx = tid + t * 256;
        int r = idx >> 5, i4 = idx & 31;
        float4 v = ((const float4*)x)[(size_t)(row0 + r) * 32 + i4];
        *((float4*)(shX + r * 132 + 4 * i4)) = v;
    }
    __syncthreads();

    const int r = tid >> 2, c = tid & 3;
    float acc[32];
    #pragma unroll
    for (int k = 0; k < 32; k++) acc[k] = 0.f;

    #pragma unroll 4
    for (int i4 = 0; i4 < 32; i4++) {
        float4 xv = *((const float4*)(shX + r * 132 + 4 * i4));
        #pragma unroll
        for (int k = 0; k < 32; k++) {
            int o = 4 * k + c;
            float4 wv = *((const float4*)(shW + o * 132 + 4 * i4));
            acc[k] = fmaf(xv.x, wv.x, acc[k]);
            acc[k] = fmaf(xv.y, wv.y, acc[k]);
            acc[k] = fmaf(xv.z, wv.z, acc[k]);
            acc[k] = fmaf(xv.w, wv.w, acc[k]);
        }
    }
    float* hrow = g_h + (size_t)(row0 + r) * FF;
    #pragma unroll
    for (int k = 0; k < 32; k++) hrow[4 * k + c] = acc[k];
}

// ---------------- Kernel B: edge terms -> factored exps (float2) ----------------
__global__ void __launch_bounds__(256) k_edge(const float* __restrict__ a_src,
                                              const float* __restrict__ a_dst) {
    int idx = blockIdx.x * 256 + threadIdx.x;
    if (idx >= BB * NN * HH) return;
    int h = idx & 3;
    int bn = idx >> 2;
    const float* hp = g_h + (size_t)bn * FF + h * DD;
    const float* as = a_src + h * DD;
    const float* ad = a_dst + h * DD;
    float es = 0.f, ed = 0.f;
    #pragma unroll
    for (int d = 0; d < DD; d++) {
        float v = hp[d];
        es = fmaf(v, as[d], es);
        ed = fmaf(v, ad[d], ed);
    }
    g_srcp[idx] = make_float2(expf(es), expf(0.2f * es));
    g_dstp[idx] = make_float2(expf(ed), expf(0.2f * ed));
}

// ---------------- Kernel B2: adj -> 64-bit row bitmasks ----------------
__global__ void __launch_bounds__(256) k_adjbit(const int* __restrict__ adj) {
    int w = (blockIdx.x * 256 + threadIdx.x) >> 5;   // 0..65535
    int lane = threadIdx.x & 31;
    int row = w >> 5;        // 0..2047
    int mt  = w & 31;        // 0..31
    const int* p = adj + (size_t)row * NN + mt * 64;
    unsigned b0 = __ballot_sync(0xffffffffu, p[lane] != 0);
    unsigned b1 = __ballot_sync(0xffffffffu, p[32 + lane] != 0);
    if (lane == 0)
        g_adjbit[row * 32 + mt] =
            (unsigned long long)b0 | ((unsigned long long)b1 << 32);
}

// ---------------- Kernel C: fused masked-softmax aggregation ----------------
// 256 threads: c = tid&7 -> head = c>>1, half = c&1; rg = tid>>3 -> rows
// row0 = n0 + 4*rg (4 rows per lane, half head = 16 cols = 8 packed accs/row).
// Weight w = exp(lrelu(es+ed)) = max(exp(es)exp(ed), exp(.2es)exp(.2ed)):
// two packed muls (row pairs) + scalar fmax, masked by adj bit (alu pipe).
// h tile swizzled q -> q ^ ((q>>3)&7): lane reads logical chunks 4c+s; per
// LDS.128 the 8 c-values in a quarter-warp map to 8 distinct bank groups.
__global__ void __launch_bounds__(256, 2) k_attn() {
    extern __shared__ char smc[];
    const unsigned smaddr = smem_u32(smc);

    const int tid  = threadIdx.x;
    const int c    = tid & 7;
    const int rg   = tid >> 3;
    const int head = c >> 1;
    const int half = c & 1;
    const int b    = blockIdx.y;
    const int z    = blockIdx.z;
    const int n0   = blockIdx.x * CROWS;
    const int row0 = n0 + 4 * rg;

    const int tile0 = (z < 5) ? 4 * z : 3 * z + 5;
    const int nt    = (z < 5) ? 4 : 3;

    // packed per-row-pair source factors
    unsigned long long spy[2], spz[2];
    #pragma unroll
    for (int p = 0; p < 2; p++) {
        float2 e0 = g_srcp[(size_t)(b * NN + row0 + 2 * p) * HH + head];
        float2 e1 = g_srcp[(size_t)(b * NN + row0 + 2 * p + 1) * HH + head];
        spy[p] = pack2f(e0.x, e1.x);
        spz[p] = pack2f(e0.y, e1.y);
    }

    unsigned long long acc[4][8];
    #pragma unroll
    for (int r = 0; r < 4; r++)
        #pragma unroll
        for (int k = 0; k < 8; k++) acc[r][k] = 0ull;
    float den[4] = {0.f, 0.f, 0.f, 0.f};

    const char* hsrc = (const char*)(g_h + (size_t)b * NN * FF);
    const char* esrc = (const char*)(g_dstp + (size_t)b * NN * HH);

    // ---- prologue: tile0 -> buffer 0 ----
    {
        int m0 = tile0 * MT;
        unsigned bufa = smaddr;
        #pragma unroll
        for (int t2 = 0; t2 < 8; t2++) {
            int gidx = tid + t2 * 256;
            int j = gidx >> 5, q = gidx & 31;
            int qs = q ^ ((q >> 3) & 7);
            cp16(bufa + OFFH + (j * 32 + qs) * 16,
                 hsrc + ((size_t)(m0 + j) * 128 + q * 4) * 4);
        }
        if (tid < 128) {
            cp16(bufa + OFFE + tid * 16, esrc + (size_t)m0 * 32 + tid * 16);
            cp8(bufa + OFFA + tid * 8,
                (const char*)g_adjbit + ((size_t)(n0 + tid) * 32 + tile0) * 8);
        }
        cp_commit();
    }

    for (int t = 0; t < nt; t++) {
        const char* buf = smc + (t & 1) * BUFB;
        cp_wait0();
        __syncthreads();   // tile t visible; all warps done with the other buffer

        if (t + 1 < nt) {  // prefetch tile t+1
            int m1 = (tile0 + t + 1) * MT;
            unsigned bufn = smaddr + ((t + 1) & 1) * BUFB;
            #pragma unroll
            for (int t2 = 0; t2 < 8; t2++) {
                int gidx = tid + t2 * 256;
                int j = gidx >> 5, q = gidx & 31;
                int qs = q ^ ((q >> 3) & 7);
                cp16(bufn + OFFH + (j * 32 + qs) * 16,
                     hsrc + ((size_t)(m1 + j) * 128 + q * 4) * 4);
            }
            if (tid < 128) {
                cp16(bufn + OFFE + tid * 16, esrc + (size_t)m1 * 32 + tid * 16);
                cp8(bufn + OFFA + tid * 8,
                    (const char*)g_adjbit +
                        ((size_t)(n0 + tid) * 32 + tile0 + t + 1) * 8);
            }
            cp_commit();
        }

        const char* sh_h = buf + OFFH;
        const float2* sh_e = (const float2*)(buf + OFFE);
        const unsigned long long* sh_m = (const unsigned long long*)(buf + OFFA);

        unsigned long long m0r = sh_m[4 * rg + 0];
        unsigned long long m1r = sh_m[4 * rg + 1];
        unsigned long long m2r = sh_m[4 * rg + 2];
        unsigned long long m3r = sh_m[4 * rg + 3];

        #pragma unroll 4
        for (int j = 0; j < MT; j++) {
            float2 ep = sh_e[j * HH + head];
            unsigned long long ey2 = pack2(ep.x);
            unsigned long long ez2 = pack2(ep.y);

            ulonglong2 hv[4];
            #pragma unroll
            for (int s = 0; s < 4; s++) {
                int q = 4 * c + s;
                int qs = q ^ ((q >> 3) & 7);
                hv[s] = *(const ulonglong2*)(sh_h + (size_t)j * 512 + qs * 16);
            }

            // pair 0: rows row0, row0+1
            {
                unsigned long long hi2 = mul2(spy[0], ey2);
                unsigned long long lo2 = mul2(spz[0], ez2);
                float h0, h1, l0, l1;
                UNPACK2(h0, h1, hi2);
                UNPACK2(l0, l1, lo2);
                float w0 = fmaxf(h0, l0);
                float w1 = fmaxf(h1, l1);
                w0 = ((m0r >> j) & 1ull) ? w0 : 0.f;
                w1 = ((m1r >> j) & 1ull) ? w1 : 0.f;
                den[0] += w0;
                den[1] += w1;
                unsigned long long w02 = pack2(w0), w12 = pack2(w1);
                #pragma unroll
                for (int s = 0; s < 4; s++) {
                    acc[0][2 * s]     = ffma2(w02, hv[s].x, acc[0][2 * s]);
                    acc[0][2 * s + 1] = ffma2(w02, hv[s].y, acc[0][2 * s + 1]);
                    acc[1][2 * s]     = ffma2(w12, hv[s].x, acc[1][2 * s]);
                    acc[1][2 * s + 1] = ffma2(w12, hv[s].y, acc[1][2 * s + 1]);
                }
            }
            // pair 1: rows row0+2, row0+3
            {
                unsigned long long hi2 = mul2(spy[1], ey2);
                unsigned long long lo2 = mul2(spz[1], ez2);
                float h0, h1, l0, l1;
                UNPACK2(h0, h1, hi2);
                UNPACK2(l0, l1, lo2);
                float w0 = fmaxf(h0, l0);
                float w1 = fmaxf(h1, l1);
                w0 = ((m2r >> j) & 1ull) ? w0 : 0.f;
                w1 = ((m3r >> j) & 1ull) ? w1 : 0.f;
                den[2] += w0;
                den[3] += w1;
                unsigned long long w02 = pack2(w0), w12 = pack2(w1);
                #pragma unroll
                for (int s = 0; s < 4; s++) {
                    acc[2][2 * s]     = ffma2(w02, hv[s].x, acc[2][2 * s]);
                    acc[2][2 * s + 1] = ffma2(w02, hv[s].y, acc[2][2 * s + 1]);
                    acc[3][2 * s]     = ffma2(w12, hv[s].x, acc[3][2 * s]);
                    acc[3][2 * s + 1] = ffma2(w12, hv[s].y, acc[3][2 * s + 1]);
                }
            }
        }
        __syncthreads();   // all warps done with buf before its refill
    }

    // ---- epilogue ----
    size_t obase = (size_t)z * (BB * NN * FF);
    #pragma unroll
    for (int r = 0; r < 4; r++) {
        ulonglong2* pr = (ulonglong2*)(g_num + obase +
                                       (size_t)(b * NN + row0 + r) * FF +
                                       head * 32 + half * 16);
        #pragma unroll
        for (int s = 0; s < 4; s++)
            pr[s] = make_ulonglong2(acc[r][2 * s], acc[r][2 * s + 1]);
    }
    if (half == 0) {
        size_t dbase = (size_t)z * (BB * NN * HH);
        #pragma unroll
        for (int r = 0; r < 4; r++)
            g_den[dbase + (size_t)(b * NN + row0 + r) * HH + head] = den[r];
    }
}

// ---------------- Kernel D: combine partials, normalize ----------------
__global__ void __launch_bounds__(256) k_combine(float* __restrict__ out) {
    int i4 = blockIdx.x * 256 + threadIdx.x;
    int bn = i4 >> 5;
    int head = (i4 >> 3) & 3;
    float sx = 0.f, sy = 0.f, sz = 0.f, sw = 0.f, den = 0.f;
    #pragma unroll
    for (int zz = 0; zz < MSPLIT; zz++) {
        float4 v = ((const float4*)(g_num + (size_t)zz * BB * NN * FF))[i4];
        sx += v.x; sy += v.y; sz += v.z; sw += v.w;
        den += g_den[(size_t)zz * BB * NN * HH + (size_t)bn * HH + head];
    }
    float inv = 1.f / den;
    ((float4*)out)[i4] = make_float4(sx * inv, sy * inv, sz * inv, sw * inv);
}

// ---------------- launch ----------------
extern "C" void kernel_launch(void* const* d_in, const int* in_sizes, int n_in,
                              void* d_out, int out_size) {
    const float* x     = (const float*)d_in[0];
    const int*   adj   = (const int*)d_in[1];
    const float* W     = (const float*)d_in[2];
    const float* a_src = (const float*)d_in[3];
    const float* a_dst = (const float*)d_in[4];
    float* out = (float*)d_out;

    cudaFuncSetAttribute(k_gemm, cudaFuncAttributeMaxDynamicSharedMemorySize, A_SMEM);
    cudaFuncSetAttribute(k_attn, cudaFuncAttributeMaxDynamicSharedMemorySize, ATTN_SMEM);

    k_adjbit<<<NN * 32 * 32 / 256, 256>>>(adj);
    k_gemm<<<(BB * NN) / 64, 256, A_SMEM>>>(x, W);
    k_edge<<<(BB * NN * HH) / 256, 256>>>(a_src, a_dst);
    dim3 gC(NN / CROWS, BB, MSPLIT);
    k_attn<<<gC, 256, ATTN_SMEM>>>();
    k_combine<<<(BB * NN * FF / 4) / 256, 256>>>(out);
}